// round 5
// baseline (speedup 1.0000x reference)
#include <cuda_runtime.h>
#include <math.h>
#include <stdint.h>

#define BATCH 2
#define T 2048
#define DM 1024
#define NH 16
#define DK 64
#define RR 8
#define LORA_SCALE 2.0f
#define MTOT (BATCH*T)      // 4096

// ---------------- scratch (device globals; no allocs allowed) ----------------
__device__ float g_weff[3][DM*DM];            // folded + tf32-rounded LoRA weights
__device__ float g_wo[DM*DM];                 // tf32-rounded Wo
__device__ float g_act[3][MTOT*DM];           // tf32-rounded q,k,v activations
__device__ float g_qkv[3][BATCH*NH*T*DK];     // Q,K,V (b,h,t,d), tf32-rounded
__device__ float g_attn[MTOT*DM];             // attention out, tf32-rounded
__device__ int   g_anyzero;                   // 1 if mask has any zero

// ---------------- helpers ----------------
__device__ __forceinline__ float tf32r(float x) {
    uint32_t r;
    asm("cvt.rna.tf32.f32 %0, %1;" : "=r"(r) : "f"(x));
    return __uint_as_float(r);
}
__device__ __forceinline__ uint32_t tf32r_u(float x) {
    uint32_t r;
    asm("cvt.rna.tf32.f32 %0, %1;" : "=r"(r) : "f"(x));
    return r;
}
#define CP_ASYNC16(dst, src) \
    asm volatile("cp.async.cg.shared.global [%0], [%1], 16;" :: "r"(dst), "l"(src))
#define CP_COMMIT() asm volatile("cp.async.commit_group;" ::: "memory")
#define CP_WAIT(n)  asm volatile("cp.async.wait_group %0;" :: "n"(n) : "memory")

__device__ __forceinline__ uint32_t smem_u32(const void* p) {
    uint32_t a;
    asm("{ .reg .u64 t; cvta.to.shared.u64 t, %1; cvt.u32.u64 %0, t; }" : "=r"(a) : "l"(p));
    return a;
}
__device__ __forceinline__ void mma_tf32(float* c, const uint32_t* a, const uint32_t* b) {
    asm volatile(
        "mma.sync.aligned.m16n8k8.row.col.f32.tf32.tf32.f32 "
        "{%0,%1,%2,%3}, {%4,%5,%6,%7}, {%8,%9}, {%0,%1,%2,%3};"
        : "+f"(c[0]), "+f"(c[1]), "+f"(c[2]), "+f"(c[3])
        : "r"(a[0]), "r"(a[1]), "r"(a[2]), "r"(a[3]), "r"(b[0]), "r"(b[1]));
}
__device__ __forceinline__ void mma_tf32b(float* c, const uint32_t* a,
                                          uint32_t b0, uint32_t b1) {
    asm volatile(
        "mma.sync.aligned.m16n8k8.row.col.f32.tf32.tf32.f32 "
        "{%0,%1,%2,%3}, {%4,%5,%6,%7}, {%8,%9}, {%0,%1,%2,%3};"
        : "+f"(c[0]), "+f"(c[1]), "+f"(c[2]), "+f"(c[3])
        : "r"(a[0]), "r"(a[1]), "r"(a[2]), "r"(a[3]), "r"(b0), "r"(b1));
}

// ---------------- mask scan ----------------
__global__ void maskscan_init() { g_anyzero = 0; }
__global__ void maskscan(const int* __restrict__ mask, int n) {
    int i = blockIdx.x * 256 + threadIdx.x;
    int z = 0;
    for (int k = i; k < n; k += gridDim.x * 256) z |= (mask[k] == 0);
    if (__any_sync(0xffffffffu, z) && (threadIdx.x & 31) == 0)
        atomicOr(&g_anyzero, 1);
}

// ---------------- W_eff = tf32_round(W + scale * B @ A) ----------------
__global__ void weff_kernel(const float* __restrict__ W,
                            const float* __restrict__ A,
                            const float* __restrict__ Bm,
                            float* __restrict__ out) {
    int idx = blockIdx.x * 256 + threadIdx.x;
    int o = idx >> 10;
    int d = idx & 1023;
    float s = 0.f;
#pragma unroll
    for (int r = 0; r < RR; r++) s += Bm[o*RR + r] * A[r*DM + d];
    out[idx] = tf32r(W[idx] + LORA_SCALE * s);
}

__global__ void round_tf32_kernel(const float* __restrict__ in,
                                  float* __restrict__ out, int n4) {
    int i = blockIdx.x * 256 + threadIdx.x;
    if (i >= n4) return;
    float4 v = ((const float4*)in)[i];
    v.x = tf32r(v.x); v.y = tf32r(v.y); v.z = tf32r(v.z); v.w = tf32r(v.w);
    ((float4*)out)[i] = v;
}

// ---------------- mma.sync tf32 GEMM, 64x64 warp tile ------------------------
// C[m,n] = sum_k A[m,k]*W[n,k] + bias[n]. All operands pre-rounded tf32.
// CTA 128x128, 4 warps (2M x 2N), warp tile 64x64, KT=16, double buffered.
// mode 0: plain C. mode 1: scatter to (b,h,t,dk), value tf32-rounded.
#define KT 16
#define NIT (DM / KT)         // 64
#define SROW 20

__global__ __launch_bounds__(128, 2)
void gemm_mma(const float* __restrict__ A, const float* __restrict__ W,
              const float* __restrict__ bias, float* __restrict__ C, int mode) {
    __shared__ float As[2][128 * SROW];
    __shared__ float Bs[2][128 * SROW];

    const int tid = threadIdx.x;
    const int wid = tid >> 5;
    const int lane = tid & 31;
    const int wm = wid >> 1;          // 0..1
    const int wn = wid & 1;           // 0..1
    const int row0 = blockIdx.y * 128;
    const int col0 = blockIdx.x * 128;

    const uint32_t sa = smem_u32(&As[0][0]);
    const uint32_t sb = smem_u32(&Bs[0][0]);
    const int e0 = tid * 4;           // 4 float4 per operand per thread
    float acc[4][8][4];
#pragma unroll
    for (int i = 0; i < 4; i++)
#pragma unroll
        for (int j = 0; j < 8; j++)
#pragma unroll
            for (int r = 0; r < 4; r++) acc[i][j][r] = 0.f;

    auto load_stage = [&](int st, int k0) {
#pragma unroll
        for (int i = 0; i < 4; i++) {
            int e = e0 + i;                 // 0..511
            int r = e >> 2;                 // row 0..127
            int c4 = (e & 3) * 4;
            uint32_t doff = (uint32_t)(r * SROW + c4) * 4;
            CP_ASYNC16(sa + (uint32_t)st * (128*SROW*4) + doff,
                       A + (size_t)(row0 + r) * DM + k0 + c4);
            CP_ASYNC16(sb + (uint32_t)st * (128*SROW*4) + doff,
                       W + (size_t)(col0 + r) * DM + k0 + c4);
        }
    };

    load_stage(0, 0);
    CP_COMMIT();

    const int arow = wm * 64 + (lane >> 2);
    const int bcol = wn * 64 + (lane >> 2);
    const int kq = lane & 3;

    for (int it = 0; it < NIT; it++) {
        if (it + 1 < NIT) {
            load_stage((it + 1) & 1, (it + 1) * KT);
            CP_COMMIT();
            CP_WAIT(1);
        } else {
            CP_WAIT(0);
        }
        __syncthreads();

        const float* as = &As[it & 1][0];
        const float* bs = &Bs[it & 1][0];
#pragma unroll
        for (int ks = 0; ks < KT; ks += 8) {
            uint32_t af[4][4];
#pragma unroll
            for (int mi = 0; mi < 4; mi++) {
                int rr = arow + mi * 16;
                af[mi][0] = __float_as_uint(as[(rr     ) * SROW + ks + kq    ]);
                af[mi][1] = __float_as_uint(as[(rr +  8) * SROW + ks + kq    ]);
                af[mi][2] = __float_as_uint(as[(rr     ) * SROW + ks + kq + 4]);
                af[mi][3] = __float_as_uint(as[(rr +  8) * SROW + ks + kq + 4]);
            }
            uint32_t bf[8][2];
#pragma unroll
            for (int ni = 0; ni < 8; ni++) {
                int cc = bcol + ni * 8;
                bf[ni][0] = __float_as_uint(bs[cc * SROW + ks + kq    ]);
                bf[ni][1] = __float_as_uint(bs[cc * SROW + ks + kq + 4]);
            }
#pragma unroll
            for (int mi = 0; mi < 4; mi++)
#pragma unroll
                for (int ni = 0; ni < 8; ni++)
                    mma_tf32(acc[mi][ni], af[mi], bf[ni]);
        }
        __syncthreads();
    }

#pragma unroll
    for (int mi = 0; mi < 4; mi++) {
        const int r_lo = row0 + wm * 64 + mi * 16 + (lane >> 2);
        const int r_hi = r_lo + 8;
#pragma unroll
        for (int ni = 0; ni < 8; ni++) {
            const int n = col0 + wn * 64 + ni * 8 + (lane & 3) * 2;
            const float2 bv = *(const float2*)(bias + n);
            float2 lo = make_float2(acc[mi][ni][0] + bv.x, acc[mi][ni][1] + bv.y);
            float2 hi = make_float2(acc[mi][ni][2] + bv.x, acc[mi][ni][3] + bv.y);
            if (mode == 0) {
                *(float2*)(C + (size_t)r_lo * DM + n) = lo;
                *(float2*)(C + (size_t)r_hi * DM + n) = hi;
            } else {
                lo.x = tf32r(lo.x); lo.y = tf32r(lo.y);
                hi.x = tf32r(hi.x); hi.y = tf32r(hi.y);
                const int h = n >> 6, dk = n & (DK - 1);
                {
                    int bb = r_lo >> 11, t = r_lo & (T - 1);
                    *(float2*)(C + (((size_t)(bb*NH + h))*T + t)*DK + dk) = lo;
                }
                {
                    int bb = r_hi >> 11, t = r_hi & (T - 1);
                    *(float2*)(C + (((size_t)(bb*NH + h))*T + t)*DK + dk) = hi;
                }
            }
        }
    }
}

// ---------------- tensor-core flash attention --------------------------------
// Inputs Q,K,V are tf32-pre-rounded. CTA 256 thr, one (b,h), 128 q rows.
#define KSTRIDE 68
#define VSTRIDE 72
#define KBYTES 17408
#define BUFBYTES 35840
#define FA_SMEM (2*BUFBYTES)    // 71680
#define NT_TILES (T/64)         // 32

__global__ __launch_bounds__(256, 2)
void flash_mma(const float* __restrict__ Q, const float* __restrict__ K,
               const float* __restrict__ V, const int* __restrict__ mask,
               float* __restrict__ O) {
    extern __shared__ float pool[];
    const int tid = threadIdx.x, wid = tid >> 5, lane = tid & 31;
    const int qt = blockIdx.x, h = blockIdx.y, b = blockIdx.z;
    const int bh = b*NH + h;
    const int r = lane >> 2, qd = lane & 3;
    const int anyz = g_anyzero;
    const uint32_t pbase = smem_u32(pool);

    // ---- stage Q, build register fragments (scale 1/8 folded; exact) ----
    {
        const float* Qg = Q + ((size_t)bh*T + (size_t)qt*128)*DK;
#pragma unroll
        for (int i = 0; i < 8; i++) {
            int e = tid + i*256;
            int row = e >> 4, c4 = (e & 15) * 4;
            CP_ASYNC16(pbase + row*(KSTRIDE*4) + c4*4, Qg + row*64 + c4);
        }
        CP_COMMIT(); CP_WAIT(0);
    }
    __syncthreads();
    uint32_t qf[8][4];
    {
        const int r0 = wid*16 + r;
#pragma unroll
        for (int ks = 0; ks < 8; ks++) {
            qf[ks][0] = __float_as_uint(pool[(r0    )*KSTRIDE + ks*8 + qd    ] * 0.125f);
            qf[ks][1] = __float_as_uint(pool[(r0 + 8)*KSTRIDE + ks*8 + qd    ] * 0.125f);
            qf[ks][2] = __float_as_uint(pool[(r0    )*KSTRIDE + ks*8 + qd + 4] * 0.125f);
            qf[ks][3] = __float_as_uint(pool[(r0 + 8)*KSTRIDE + ks*8 + qd + 4] * 0.125f);
        }
    }
    __syncthreads();

    const float* Kg = K + (size_t)bh*T*DK;
    const float* Vg = V + (size_t)bh*T*DK;

    auto loadKV = [&](int kt, int bufb) {
        const float* kg = Kg + (size_t)kt*64*DK;
        const float* vg = Vg + (size_t)kt*64*DK;
        uint32_t kb = pbase + (uint32_t)bufb * BUFBYTES;
        uint32_t vb = kb + KBYTES;
#pragma unroll
        for (int i = 0; i < 4; i++) {
            int e = tid + i*256;
            int row = e >> 4, c4 = (e & 15) * 4;
            CP_ASYNC16(kb + row*(KSTRIDE*4) + c4*4, kg + row*64 + c4);
            CP_ASYNC16(vb + row*(VSTRIDE*4) + c4*4, vg + row*64 + c4);
        }
    };

    float m_lo = -1e30f, m_hi = -1e30f, l_lo = 0.f, l_hi = 0.f;
    float oacc[8][4];
#pragma unroll
    for (int i = 0; i < 8; i++)
#pragma unroll
        for (int j = 0; j < 4; j++) oacc[i][j] = 0.f;

    const int q0 = qt*128 + wid*16;
    const int s1 = (lane & 28) | (qd >> 1);
    const int s2 = s1 + 2;
    const bool odd = (qd & 1) != 0;

    loadKV(0, 0);
    CP_COMMIT();

    for (int kt = 0; kt < NT_TILES; kt++) {
        const int buf = kt & 1;
        if (kt + 1 < NT_TILES) {
            loadKV(kt + 1, buf ^ 1);
            CP_COMMIT();
            CP_WAIT(1);
        } else {
            CP_WAIT(0);
        }
        __syncthreads();

        const float* ksm = pool + buf * (BUFBYTES/4);
        const float* vsm = ksm + (KBYTES/4);

        // ---- S = Q K^T (K pre-rounded: plain LDS) ----
        float sa[8][4];
#pragma unroll
        for (int i = 0; i < 8; i++)
#pragma unroll
            for (int j = 0; j < 4; j++) sa[i][j] = 0.f;
#pragma unroll
        for (int ks = 0; ks < 8; ks++) {
#pragma unroll
            for (int nt = 0; nt < 8; nt++) {
                uint32_t b0 = __float_as_uint(ksm[(nt*8 + r)*KSTRIDE + ks*8 + qd    ]);
                uint32_t b1 = __float_as_uint(ksm[(nt*8 + r)*KSTRIDE + ks*8 + qd + 4]);
                mma_tf32b(sa[nt], qf[ks], b0, b1);
            }
        }

        if (anyz) {
#pragma unroll
            for (int nt = 0; nt < 8; nt++) {
                const int col = kt*64 + nt*8 + qd*2;
                int2 mlo = *(const int2*)(mask + (size_t)(q0 + r    )*T + col);
                int2 mhi = *(const int2*)(mask + (size_t)(q0 + r + 8)*T + col);
                if (mlo.x == 0) sa[nt][0] = -1e9f;
                if (mlo.y == 0) sa[nt][1] = -1e9f;
                if (mhi.x == 0) sa[nt][2] = -1e9f;
                if (mhi.y == 0) sa[nt][3] = -1e9f;
            }
        }

        // ---- online softmax ----
        float tm_lo = m_lo, tm_hi = m_hi;
#pragma unroll
        for (int nt = 0; nt < 8; nt++) {
            tm_lo = fmaxf(tm_lo, fmaxf(sa[nt][0], sa[nt][1]));
            tm_hi = fmaxf(tm_hi, fmaxf(sa[nt][2], sa[nt][3]));
        }
        tm_lo = fmaxf(tm_lo, __shfl_xor_sync(0xffffffffu, tm_lo, 1));
        tm_lo = fmaxf(tm_lo, __shfl_xor_sync(0xffffffffu, tm_lo, 2));
        tm_hi = fmaxf(tm_hi, __shfl_xor_sync(0xffffffffu, tm_hi, 1));
        tm_hi = fmaxf(tm_hi, __shfl_xor_sync(0xffffffffu, tm_hi, 2));
        const float corr_lo = __expf(m_lo - tm_lo);
        const float corr_hi = __expf(m_hi - tm_hi);
        m_lo = tm_lo; m_hi = tm_hi;

        float suml_lo = 0.f, suml_hi = 0.f;
#pragma unroll
        for (int nt = 0; nt < 8; nt++) {
            sa[nt][0] = __expf(sa[nt][0] - m_lo);
            sa[nt][1] = __expf(sa[nt][1] - m_lo);
            sa[nt][2] = __expf(sa[nt][2] - m_hi);
            sa[nt][3] = __expf(sa[nt][3] - m_hi);
            suml_lo += sa[nt][0] + sa[nt][1];
            suml_hi += sa[nt][2] + sa[nt][3];
        }
        suml_lo += __shfl_xor_sync(0xffffffffu, suml_lo, 1);
        suml_lo += __shfl_xor_sync(0xffffffffu, suml_lo, 2);
        suml_hi += __shfl_xor_sync(0xffffffffu, suml_hi, 1);
        suml_hi += __shfl_xor_sync(0xffffffffu, suml_hi, 2);
        l_lo = l_lo * corr_lo + suml_lo;
        l_hi = l_hi * corr_hi + suml_hi;
#pragma unroll
        for (int nt = 0; nt < 8; nt++) {
            oacc[nt][0] *= corr_lo; oacc[nt][1] *= corr_lo;
            oacc[nt][2] *= corr_hi; oacc[nt][3] *= corr_hi;
        }

        // ---- O += P V ----
#pragma unroll
        for (int j = 0; j < 8; j++) {
            float x0 = __shfl_sync(0xffffffffu, sa[j][0], s1);
            float x1 = __shfl_sync(0xffffffffu, sa[j][1], s1);
            float x2 = __shfl_sync(0xffffffffu, sa[j][2], s1);
            float x3 = __shfl_sync(0xffffffffu, sa[j][3], s1);
            float y0 = __shfl_sync(0xffffffffu, sa[j][0], s2);
            float y1 = __shfl_sync(0xffffffffu, sa[j][1], s2);
            float y2 = __shfl_sync(0xffffffffu, sa[j][2], s2);
            float y3 = __shfl_sync(0xffffffffu, sa[j][3], s2);
            uint32_t af[4];
            af[0] = tf32r_u(odd ? x1 : x0);
            af[1] = tf32r_u(odd ? x3 : x2);
            af[2] = tf32r_u(odd ? y1 : y0);
            af[3] = tf32r_u(odd ? y3 : y2);
#pragma unroll
            for (int nt = 0; nt < 8; nt++) {
                uint32_t b0 = __float_as_uint(vsm[(j*8 + qd    )*VSTRIDE + nt*8 + r]);
                uint32_t b1 = __float_as_uint(vsm[(j*8 + qd + 4)*VSTRIDE + nt*8 + r]);
                mma_tf32b(oacc[nt], af, b0, b1);
            }
        }
        __syncthreads();
    }

    // ---- epilogue: O -> (b, t, h*64+d), tf32-rounded for Wo GEMM ----
    const float ilo = 1.f / l_lo;
    const float ihi = 1.f / l_hi;
#pragma unroll
    for (int nt = 0; nt < 8; nt++) {
        const int col = h*64 + nt*8 + qd*2;
        float2 lo = make_float2(tf32r(oacc[nt][0]*ilo), tf32r(oacc[nt][1]*ilo));
        float2 hi = make_float2(tf32r(oacc[nt][2]*ihi), tf32r(oacc[nt][3]*ihi));
        *(float2*)(O + (size_t)(b*T + q0 + r    )*DM + col) = lo;
        *(float2*)(O + (size_t)(b*T + q0 + r + 8)*DM + col) = hi;
    }
}

// ---------------- launch ----------------
extern "C" void kernel_launch(void* const* d_in, const int* in_sizes, int n_in,
                              void* d_out, int out_size) {
    const float* q    = (const float*)d_in[0];
    const float* k    = (const float*)d_in[1];
    const float* v    = (const float*)d_in[2];
    const int*   mask = (const int*)  d_in[3];
    const float* Wq = (const float*)d_in[4],  *bq = (const float*)d_in[5];
    const float* Aq = (const float*)d_in[6],  *Bq = (const float*)d_in[7];
    const float* Wk = (const float*)d_in[8],  *bk = (const float*)d_in[9];
    const float* Ak = (const float*)d_in[10], *Bk = (const float*)d_in[11];
    const float* Wv = (const float*)d_in[12], *bv = (const float*)d_in[13];
    const float* Av = (const float*)d_in[14], *Bv = (const float*)d_in[15];
    const float* Wo = (const float*)d_in[16], *bo = (const float*)d_in[17];
    float* out = (float*)d_out;

    float *weff, *wo, *act, *qkv, *attn;
    cudaGetSymbolAddress((void**)&weff, g_weff);
    cudaGetSymbolAddress((void**)&wo,   g_wo);
    cudaGetSymbolAddress((void**)&act,  g_act);
    cudaGetSymbolAddress((void**)&qkv,  g_qkv);
    cudaGetSymbolAddress((void**)&attn, g_attn);

    float* weffq = weff;
    float* weffk = weff + (size_t)DM*DM;
    float* weffv = weff + (size_t)2*DM*DM;
    float* aq = act;
    float* ak = act + (size_t)MTOT*DM;
    float* av = act + (size_t)2*MTOT*DM;
    const size_t QKV_SZ = (size_t)BATCH*NH*T*DK;
    float* Qp = qkv;
    float* Kp = qkv + QKV_SZ;
    float* Vp = qkv + 2*QKV_SZ;

    cudaFuncSetAttribute(flash_mma, cudaFuncAttributeMaxDynamicSharedMemorySize, FA_SMEM);

    maskscan_init<<<1, 1>>>();
    maskscan<<<4096, 256>>>(mask, T*T);

    weff_kernel<<<DM*DM/256, 256>>>(Wq, Aq, Bq, weffq);
    weff_kernel<<<DM*DM/256, 256>>>(Wk, Ak, Bk, weffk);
    weff_kernel<<<DM*DM/256, 256>>>(Wv, Av, Bv, weffv);
    round_tf32_kernel<<<DM*DM/4/256, 256>>>(Wo, wo, DM*DM/4);
    round_tf32_kernel<<<MTOT*DM/4/256, 256>>>(q, aq, MTOT*DM/4);
    round_tf32_kernel<<<MTOT*DM/4/256, 256>>>(k, ak, MTOT*DM/4);
    round_tf32_kernel<<<MTOT*DM/4/256, 256>>>(v, av, MTOT*DM/4);

    dim3 gg(DM/128, MTOT/128);     // 8 x 32
    gemm_mma<<<gg, 128>>>(aq, weffq, bq, Qp, 1);
    gemm_mma<<<gg, 128>>>(ak, weffk, bk, Kp, 1);
    gemm_mma<<<gg, 128>>>(av, weffv, bv, Vp, 1);

    flash_mma<<<dim3(T/128, NH, BATCH), 256, FA_SMEM>>>(Qp, Kp, Vp, mask, attn);

    gemm_mma<<<gg, 128>>>(attn, wo, bo, out, 0);
}

// round 6
// speedup vs baseline: 1.3119x; 1.3119x over previous
#include <cuda_runtime.h>
#include <math.h>
#include <stdint.h>

#define BATCH 2
#define T 2048
#define DM 1024
#define NH 16
#define DK 64
#define RR 8
#define LORA_SCALE 2.0f
#define MTOT (BATCH*T)      // 4096

// ---------------- scratch ----------------
__device__ float g_weff[3][DM*DM];
__device__ float g_wo[DM*DM];
__device__ float g_qkv[3][BATCH*NH*T*DK];
__device__ float g_attn[MTOT*DM];
__device__ int   g_anyzero;

// ---------------- helpers ----------------
__device__ __forceinline__ float tf32r(float x) {
    uint32_t r;
    asm("cvt.rna.tf32.f32 %0, %1;" : "=r"(r) : "f"(x));
    return __uint_as_float(r);
}
__device__ __forceinline__ uint32_t tf32r_u(float x) {
    uint32_t r;
    asm("cvt.rna.tf32.f32 %0, %1;" : "=r"(r) : "f"(x));
    return r;
}
#define CP_ASYNC16(dst, src) \
    asm volatile("cp.async.cg.shared.global [%0], [%1], 16;" :: "r"(dst), "l"(src))
#define CP_COMMIT() asm volatile("cp.async.commit_group;" ::: "memory")
#define CP_WAIT(n)  asm volatile("cp.async.wait_group %0;" :: "n"(n) : "memory")

__device__ __forceinline__ uint32_t smem_u32(const void* p) {
    uint32_t a;
    asm("{ .reg .u64 t; cvta.to.shared.u64 t, %1; cvt.u32.u64 %0, t; }" : "=r"(a) : "l"(p));
    return a;
}
__device__ __forceinline__ void mma_tf32(float* c, const uint32_t* a, const uint32_t* b) {
    asm volatile(
        "mma.sync.aligned.m16n8k8.row.col.f32.tf32.tf32.f32 "
        "{%0,%1,%2,%3}, {%4,%5,%6,%7}, {%8,%9}, {%0,%1,%2,%3};"
        : "+f"(c[0]), "+f"(c[1]), "+f"(c[2]), "+f"(c[3])
        : "r"(a[0]), "r"(a[1]), "r"(a[2]), "r"(a[3]), "r"(b[0]), "r"(b[1]));
}
__device__ __forceinline__ void mma_tf32b(float* c, const uint32_t* a,
                                          uint32_t b0, uint32_t b1) {
    asm volatile(
        "mma.sync.aligned.m16n8k8.row.col.f32.tf32.tf32.f32 "
        "{%0,%1,%2,%3}, {%4,%5,%6,%7}, {%8,%9}, {%0,%1,%2,%3};"
        : "+f"(c[0]), "+f"(c[1]), "+f"(c[2]), "+f"(c[3])
        : "r"(a[0]), "r"(a[1]), "r"(a[2]), "r"(a[3]), "r"(b0), "r"(b1));
}

// ---------------- mask scan ----------------
__global__ void maskscan_init() { g_anyzero = 0; }
__global__ void maskscan(const int* __restrict__ mask, int n) {
    int i = blockIdx.x * 256 + threadIdx.x;
    int z = 0;
    for (int k = i; k < n; k += gridDim.x * 256) z |= (mask[k] == 0);
    if (__any_sync(0xffffffffu, z) && (threadIdx.x & 31) == 0)
        atomicOr(&g_anyzero, 1);
}

// ---------------- W_eff = tf32_round(W + scale * B @ A) ----------------
__global__ void weff_kernel(const float* __restrict__ W,
                            const float* __restrict__ A,
                            const float* __restrict__ Bm,
                            float* __restrict__ out) {
    int idx = blockIdx.x * 256 + threadIdx.x;
    int o = idx >> 10;
    int d = idx & 1023;
    float s = 0.f;
#pragma unroll
    for (int r = 0; r < RR; r++) s += Bm[o*RR + r] * A[r*DM + d];
    out[idx] = tf32r(W[idx] + LORA_SCALE * s);
}

__global__ void round_tf32_kernel(const float* __restrict__ in,
                                  float* __restrict__ out, int n4) {
    int i = blockIdx.x * 256 + threadIdx.x;
    if (i >= n4) return;
    float4 v = ((const float4*)in)[i];
    v.x = tf32r(v.x); v.y = tf32r(v.y); v.z = tf32r(v.z); v.w = tf32r(v.w);
    ((float4*)out)[i] = v;
}

// ---------------- mma.sync tf32 GEMM, 3-stage, KT=32, 1 sync/iter -----------
// C[m,n] = sum_k A[m,k]*W[n,k] + bias[n]. W pre-rounded tf32; A rounded here.
// CTA 128x128, 8 warps (2M x 4N), warp tile 64x32. Batched over blockIdx.z.
// mode 0: plain C. mode 1: scatter to (b,h,t,dk), value tf32-rounded.
#define KT 32
#define NIT (DM / KT)          // 32
#define SROW 36                // 32 + 4 pad: banks (4r+k)%32 conflict-free
#define STG_F (128 * SROW)     // floats per operand per stage
#define GEMM_SMEM (3 * 2 * STG_F * 4)   // 110592 B

__global__ __launch_bounds__(256, 2)
void gemm_mma(const float* __restrict__ A0, const float* __restrict__ A1,
              const float* __restrict__ A2,
              const float* __restrict__ W0, const float* __restrict__ W1,
              const float* __restrict__ W2,
              const float* __restrict__ b0, const float* __restrict__ b1,
              const float* __restrict__ b2,
              float* __restrict__ C0, float* __restrict__ C1,
              float* __restrict__ C2, int mode) {
    extern __shared__ float smp[];
    const int z = blockIdx.z;
    const float* A   = (z == 0) ? A0 : (z == 1) ? A1 : A2;
    const float* W   = (z == 0) ? W0 : (z == 1) ? W1 : W2;
    const float* bia = (z == 0) ? b0 : (z == 1) ? b1 : b2;
    float*       C   = (z == 0) ? C0 : (z == 1) ? C1 : C2;

    const int tid = threadIdx.x;
    const int wid = tid >> 5;
    const int lane = tid & 31;
    const int wm = wid >> 2;
    const int wn = wid & 3;
    const int row0 = blockIdx.y * 128;
    const int col0 = blockIdx.x * 128;

    const uint32_t sbase = smem_u32(smp);

    float acc[4][4][4];
#pragma unroll
    for (int i = 0; i < 4; i++)
#pragma unroll
        for (int j = 0; j < 4; j++)
#pragma unroll
            for (int r = 0; r < 4; r++) acc[i][j][r] = 0.f;

    // stage loader: 1024 float4 per operand, 256 thr -> 4 each
    auto load_stage = [&](int g) {
        const int st = g % 3;
        const int k0 = g * KT;
        const uint32_t abase = sbase + (uint32_t)st * (2*STG_F*4);
        const uint32_t bbase = abase + STG_F*4;
#pragma unroll
        for (int i = 0; i < 4; i++) {
            int e = tid + i * 256;          // 0..1023
            int r = e >> 3;                 // 0..127
            int c4 = (e & 7) * 4;           // 0..28
            uint32_t doff = (uint32_t)(r * SROW + c4) * 4;
            CP_ASYNC16(abase + doff, A + (size_t)(row0 + r) * DM + k0 + c4);
            CP_ASYNC16(bbase + doff, W + (size_t)(col0 + r) * DM + k0 + c4);
        }
        CP_COMMIT();
    };

    load_stage(0);
    load_stage(1);

    const int arow = wm * 64 + (lane >> 2);
    const int bcol = wn * 32 + (lane >> 2);
    const int kq = lane & 3;

    for (int it = 0; it < NIT; it++) {
        if (it + 1 < NIT) { CP_WAIT(1); } else { CP_WAIT(0); }
        __syncthreads();
        if (it + 2 < NIT) load_stage(it + 2);

        const float* as = smp + (it % 3) * (2*STG_F);
        const float* bs = as + STG_F;
#pragma unroll
        for (int ks = 0; ks < KT; ks += 8) {
            uint32_t af[4][4];
#pragma unroll
            for (int mi = 0; mi < 4; mi++) {
                int rr = arow + mi * 16;
                af[mi][0] = tf32r_u(as[(rr     ) * SROW + ks + kq    ]);
                af[mi][1] = tf32r_u(as[(rr +  8) * SROW + ks + kq    ]);
                af[mi][2] = tf32r_u(as[(rr     ) * SROW + ks + kq + 4]);
                af[mi][3] = tf32r_u(as[(rr +  8) * SROW + ks + kq + 4]);
            }
            uint32_t bf[4][2];
#pragma unroll
            for (int ni = 0; ni < 4; ni++) {
                int cc = bcol + ni * 8;
                bf[ni][0] = __float_as_uint(bs[cc * SROW + ks + kq    ]);
                bf[ni][1] = __float_as_uint(bs[cc * SROW + ks + kq + 4]);
            }
#pragma unroll
            for (int mi = 0; mi < 4; mi++)
#pragma unroll
                for (int ni = 0; ni < 4; ni++)
                    mma_tf32(acc[mi][ni], af[mi], bf[ni]);
        }
    }

#pragma unroll
    for (int mi = 0; mi < 4; mi++) {
        const int r_lo = row0 + wm * 64 + mi * 16 + (lane >> 2);
        const int r_hi = r_lo + 8;
#pragma unroll
        for (int ni = 0; ni < 4; ni++) {
            const int n = col0 + wn * 32 + ni * 8 + (lane & 3) * 2;
            const float2 bv = *(const float2*)(bia + n);
            float2 lo = make_float2(acc[mi][ni][0] + bv.x, acc[mi][ni][1] + bv.y);
            float2 hi = make_float2(acc[mi][ni][2] + bv.x, acc[mi][ni][3] + bv.y);
            if (mode == 0) {
                *(float2*)(C + (size_t)r_lo * DM + n) = lo;
                *(float2*)(C + (size_t)r_hi * DM + n) = hi;
            } else {
                lo.x = tf32r(lo.x); lo.y = tf32r(lo.y);
                hi.x = tf32r(hi.x); hi.y = tf32r(hi.y);
                const int h = n >> 6, dk = n & (DK - 1);
                {
                    int bb = r_lo >> 11, t = r_lo & (T - 1);
                    *(float2*)(C + (((size_t)(bb*NH + h))*T + t)*DK + dk) = lo;
                }
                {
                    int bb = r_hi >> 11, t = r_hi & (T - 1);
                    *(float2*)(C + (((size_t)(bb*NH + h))*T + t)*DK + dk) = hi;
                }
            }
        }
    }
}

// ---------------- tensor-core flash attention (R5, CVT-free inner loops) ----
#define KSTRIDE 68
#define VSTRIDE 72
#define KBYTES 17408
#define BUFBYTES 35840
#define FA_SMEM (2*BUFBYTES)    // 71680
#define NT_TILES (T/64)         // 32

__global__ __launch_bounds__(256, 2)
void flash_mma(const float* __restrict__ Q, const float* __restrict__ K,
               const float* __restrict__ V, const int* __restrict__ mask,
               float* __restrict__ O) {
    extern __shared__ float pool[];
    const int tid = threadIdx.x, wid = tid >> 5, lane = tid & 31;
    const int qt = blockIdx.x, h = blockIdx.y, b = blockIdx.z;
    const int bh = b*NH + h;
    const int r = lane >> 2, qd = lane & 3;
    const int anyz = g_anyzero;
    const uint32_t pbase = smem_u32(pool);

    {
        const float* Qg = Q + ((size_t)bh*T + (size_t)qt*128)*DK;
#pragma unroll
        for (int i = 0; i < 8; i++) {
            int e = tid + i*256;
            int row = e >> 4, c4 = (e & 15) * 4;
            CP_ASYNC16(pbase + row*(KSTRIDE*4) + c4*4, Qg + row*64 + c4);
        }
        CP_COMMIT(); CP_WAIT(0);
    }
    __syncthreads();
    uint32_t qf[8][4];
    {
        const int r0 = wid*16 + r;
#pragma unroll
        for (int ks = 0; ks < 8; ks++) {
            qf[ks][0] = __float_as_uint(pool[(r0    )*KSTRIDE + ks*8 + qd    ] * 0.125f);
            qf[ks][1] = __float_as_uint(pool[(r0 + 8)*KSTRIDE + ks*8 + qd    ] * 0.125f);
            qf[ks][2] = __float_as_uint(pool[(r0    )*KSTRIDE + ks*8 + qd + 4] * 0.125f);
            qf[ks][3] = __float_as_uint(pool[(r0 + 8)*KSTRIDE + ks*8 + qd + 4] * 0.125f);
        }
    }
    __syncthreads();

    const float* Kg = K + (size_t)bh*T*DK;
    const float* Vg = V + (size_t)bh*T*DK;

    auto loadKV = [&](int kt, int bufb) {
        const float* kg = Kg + (size_t)kt*64*DK;
        const float* vg = Vg + (size_t)kt*64*DK;
        uint32_t kb = pbase + (uint32_t)bufb * BUFBYTES;
        uint32_t vb = kb + KBYTES;
#pragma unroll
        for (int i = 0; i < 4; i++) {
            int e = tid + i*256;
            int row = e >> 4, c4 = (e & 15) * 4;
            CP_ASYNC16(kb + row*(KSTRIDE*4) + c4*4, kg + row*64 + c4);
            CP_ASYNC16(vb + row*(VSTRIDE*4) + c4*4, vg + row*64 + c4);
        }
    };

    float m_lo = -1e30f, m_hi = -1e30f, l_lo = 0.f, l_hi = 0.f;
    float oacc[8][4];
#pragma unroll
    for (int i = 0; i < 8; i++)
#pragma unroll
        for (int j = 0; j < 4; j++) oacc[i][j] = 0.f;

    const int q0 = qt*128 + wid*16;
    const int s1 = (lane & 28) | (qd >> 1);
    const int s2 = s1 + 2;
    const bool odd = (qd & 1) != 0;

    loadKV(0, 0);
    CP_COMMIT();

    for (int kt = 0; kt < NT_TILES; kt++) {
        const int buf = kt & 1;
        if (kt + 1 < NT_TILES) {
            loadKV(kt + 1, buf ^ 1);
            CP_COMMIT();
            CP_WAIT(1);
        } else {
            CP_WAIT(0);
        }
        __syncthreads();

        const float* ksm = pool + buf * (BUFBYTES/4);
        const float* vsm = ksm + (KBYTES/4);

        float sa[8][4];
#pragma unroll
        for (int i = 0; i < 8; i++)
#pragma unroll
            for (int j = 0; j < 4; j++) sa[i][j] = 0.f;
#pragma unroll
        for (int ks = 0; ks < 8; ks++) {
#pragma unroll
            for (int nt = 0; nt < 8; nt++) {
                uint32_t b0 = __float_as_uint(ksm[(nt*8 + r)*KSTRIDE + ks*8 + qd    ]);
                uint32_t b1 = __float_as_uint(ksm[(nt*8 + r)*KSTRIDE + ks*8 + qd + 4]);
                mma_tf32b(sa[nt], qf[ks], b0, b1);
            }
        }

        if (anyz) {
#pragma unroll
            for (int nt = 0; nt < 8; nt++) {
                const int col = kt*64 + nt*8 + qd*2;
                int2 mlo = *(const int2*)(mask + (size_t)(q0 + r    )*T + col);
                int2 mhi = *(const int2*)(mask + (size_t)(q0 + r + 8)*T + col);
                if (mlo.x == 0) sa[nt][0] = -1e9f;
                if (mlo.y == 0) sa[nt][1] = -1e9f;
                if (mhi.x == 0) sa[nt][2] = -1e9f;
                if (mhi.y == 0) sa[nt][3] = -1e9f;
            }
        }

        float tm_lo = m_lo, tm_hi = m_hi;
#pragma unroll
        for (int nt = 0; nt < 8; nt++) {
            tm_lo = fmaxf(tm_lo, fmaxf(sa[nt][0], sa[nt][1]));
            tm_hi = fmaxf(tm_hi, fmaxf(sa[nt][2], sa[nt][3]));
        }
        tm_lo = fmaxf(tm_lo, __shfl_xor_sync(0xffffffffu, tm_lo, 1));
        tm_lo = fmaxf(tm_lo, __shfl_xor_sync(0xffffffffu, tm_lo, 2));
        tm_hi = fmaxf(tm_hi, __shfl_xor_sync(0xffffffffu, tm_hi, 1));
        tm_hi = fmaxf(tm_hi, __shfl_xor_sync(0xffffffffu, tm_hi, 2));
        const float corr_lo = __expf(m_lo - tm_lo);
        const float corr_hi = __expf(m_hi - tm_hi);
        m_lo = tm_lo; m_hi = tm_hi;

        float suml_lo = 0.f, suml_hi = 0.f;
#pragma unroll
        for (int nt = 0; nt < 8; nt++) {
            sa[nt][0] = __expf(sa[nt][0] - m_lo);
            sa[nt][1] = __expf(sa[nt][1] - m_lo);
            sa[nt][2] = __expf(sa[nt][2] - m_hi);
            sa[nt][3] = __expf(sa[nt][3] - m_hi);
            suml_lo += sa[nt][0] + sa[nt][1];
            suml_hi += sa[nt][2] + sa[nt][3];
        }
        suml_lo += __shfl_xor_sync(0xffffffffu, suml_lo, 1);
        suml_lo += __shfl_xor_sync(0xffffffffu, suml_lo, 2);
        suml_hi += __shfl_xor_sync(0xffffffffu, suml_hi, 1);
        suml_hi += __shfl_xor_sync(0xffffffffu, suml_hi, 2);
        l_lo = l_lo * corr_lo + suml_lo;
        l_hi = l_hi * corr_hi + suml_hi;
#pragma unroll
        for (int nt = 0; nt < 8; nt++) {
            oacc[nt][0] *= corr_lo; oacc[nt][1] *= corr_lo;
            oacc[nt][2] *= corr_hi; oacc[nt][3] *= corr_hi;
        }

#pragma unroll
        for (int j = 0; j < 8; j++) {
            float x0 = __shfl_sync(0xffffffffu, sa[j][0], s1);
            float x1 = __shfl_sync(0xffffffffu, sa[j][1], s1);
            float x2 = __shfl_sync(0xffffffffu, sa[j][2], s1);
            float x3 = __shfl_sync(0xffffffffu, sa[j][3], s1);
            float y0 = __shfl_sync(0xffffffffu, sa[j][0], s2);
            float y1 = __shfl_sync(0xffffffffu, sa[j][1], s2);
            float y2 = __shfl_sync(0xffffffffu, sa[j][2], s2);
            float y3 = __shfl_sync(0xffffffffu, sa[j][3], s2);
            uint32_t af[4];
            af[0] = tf32r_u(odd ? x1 : x0);
            af[1] = tf32r_u(odd ? x3 : x2);
            af[2] = tf32r_u(odd ? y1 : y0);
            af[3] = tf32r_u(odd ? y3 : y2);
#pragma unroll
            for (int nt = 0; nt < 8; nt++) {
                uint32_t b0 = __float_as_uint(vsm[(j*8 + qd    )*VSTRIDE + nt*8 + r]);
                uint32_t b1 = __float_as_uint(vsm[(j*8 + qd + 4)*VSTRIDE + nt*8 + r]);
                mma_tf32b(oacc[nt], af, b0, b1);
            }
        }
        __syncthreads();
    }

    const float ilo = 1.f / l_lo;
    const float ihi = 1.f / l_hi;
#pragma unroll
    for (int nt = 0; nt < 8; nt++) {
        const int col = h*64 + nt*8 + qd*2;
        float2 lo = make_float2(tf32r(oacc[nt][0]*ilo), tf32r(oacc[nt][1]*ilo));
        float2 hi = make_float2(tf32r(oacc[nt][2]*ihi), tf32r(oacc[nt][3]*ihi));
        *(float2*)(O + (size_t)(b*T + q0 + r    )*DM + col) = lo;
        *(float2*)(O + (size_t)(b*T + q0 + r + 8)*DM + col) = hi;
    }
}

// ---------------- launch ----------------
extern "C" void kernel_launch(void* const* d_in, const int* in_sizes, int n_in,
                              void* d_out, int out_size) {
    const float* q    = (const float*)d_in[0];
    const float* k    = (const float*)d_in[1];
    const float* v    = (const float*)d_in[2];
    const int*   mask = (const int*)  d_in[3];
    const float* Wq = (const float*)d_in[4],  *bq = (const float*)d_in[5];
    const float* Aq = (const float*)d_in[6],  *Bq = (const float*)d_in[7];
    const float* Wk = (const float*)d_in[8],  *bk = (const float*)d_in[9];
    const float* Ak = (const float*)d_in[10], *Bk = (const float*)d_in[11];
    const float* Wv = (const float*)d_in[12], *bv = (const float*)d_in[13];
    const float* Av = (const float*)d_in[14], *Bv = (const float*)d_in[15];
    const float* Wo = (const float*)d_in[16], *bo = (const float*)d_in[17];
    float* out = (float*)d_out;

    float *weff, *wo, *qkv, *attn;
    cudaGetSymbolAddress((void**)&weff, g_weff);
    cudaGetSymbolAddress((void**)&wo,   g_wo);
    cudaGetSymbolAddress((void**)&qkv,  g_qkv);
    cudaGetSymbolAddress((void**)&attn, g_attn);

    float* weffq = weff;
    float* weffk = weff + (size_t)DM*DM;
    float* weffv = weff + (size_t)2*DM*DM;
    const size_t QKV_SZ = (size_t)BATCH*NH*T*DK;
    float* Qp = qkv;
    float* Kp = qkv + QKV_SZ;
    float* Vp = qkv + 2*QKV_SZ;

    cudaFuncSetAttribute(gemm_mma, cudaFuncAttributeMaxDynamicSharedMemorySize, GEMM_SMEM);
    cudaFuncSetAttribute(flash_mma, cudaFuncAttributeMaxDynamicSharedMemorySize, FA_SMEM);

    // launches 1-4: prep; launch 5: batched QKV GEMM (ncu -s 5 lands here)
    weff_kernel<<<DM*DM/256, 256>>>(Wq, Aq, Bq, weffq);
    weff_kernel<<<DM*DM/256, 256>>>(Wk, Ak, Bk, weffk);
    weff_kernel<<<DM*DM/256, 256>>>(Wv, Av, Bv, weffv);
    round_tf32_kernel<<<DM*DM/4/256, 256>>>(Wo, wo, DM*DM/4);

    dim3 gqkv(DM/128, MTOT/128, 3);   // 8 x 32 x 3
    gemm_mma<<<gqkv, 256, GEMM_SMEM>>>(q, k, v, weffq, weffk, weffv,
                                       bq, bk, bv, Qp, Kp, Vp, 1);

    maskscan_init<<<1, 1>>>();
    maskscan<<<4096, 256>>>(mask, T*T);

    flash_mma<<<dim3(T/128, NH, BATCH), 256, FA_SMEM>>>(Qp, Kp, Vp, mask, attn);

    dim3 go(DM/128, MTOT/128, 1);
    gemm_mma<<<go, 256, GEMM_SMEM>>>(attn, attn, attn, wo, wo, wo,
                                     bo, bo, bo, out, out, out, 0);
}